// round 16
// baseline (speedup 1.0000x reference)
#include <cuda_runtime.h>
#include <cuda_bf16.h>
#include <math.h>

// ---------------------------------------------------------------------------
// SelfAttention: bs=4, n=2048, D=1024, H=8, dh=128
// Round 16 (= round 14/15 resubmit after broker timeouts):
// round-13 + ldmatrix fragment loads (48 LDS.32 -> 12 LDSM.x4 per warp per
// 16-k slice; shared pipe was the top pipe at 48.8% in round 12).
// Pre-split bf16 hi/lo operands in GMEM, pure cp.async staging, 2 CTAs/SM.
// All GEMMs: mma.sync m16n8k16 bf16, 3-MMA hi/lo split, f32 accumulate.
// d_out layout: [ out (4*2048*1024) | A_last (4*2048*2048) ]
// ---------------------------------------------------------------------------

namespace {
constexpr int BSZ  = 4;
constexpr int NSEQ = 2048;
constexpr int DM   = 1024;
constexpr int NH   = 8;
constexpr int DH   = 128;
constexpr float NEG_INF_F = -1e9f;
constexpr size_t OUT_A_OFF = (size_t)BSZ * NSEQ * DM;
constexpr int LDK  = 40;                     // smem row stride (32 + 8 pad), bf16
constexpr int TILE = 128 * LDK;              // one matrix tile, elems
constexpr int SSTR = 4 * TILE;               // one stage = Ah,Al,Bh,Bl
constexpr int SMEM_BYTES = 2 * SSTR * 2;     // two stages -> 81920 B
}

// ---- device-global scratch (no allocations allowed) ----
__device__ float  g_AP[(size_t)NSEQ * NSEQ];                      // 16 MB
__device__ float2 g_Wf[DM];
__device__ float  g_S [(size_t)BSZ * NH * NSEQ * NSEQ];           // 536 MB fp32
// bf16 hi/lo pairs
__device__ __nv_bfloat16 g_xh [(size_t)BSZ * NSEQ * DM], g_xl [(size_t)BSZ * NSEQ * DM];
__device__ __nv_bfloat16 g_Wqh[DM * DM], g_Wql[DM * DM];
__device__ __nv_bfloat16 g_Wkh[DM * DM], g_Wkl[DM * DM];
__device__ __nv_bfloat16 g_Wvh[DM * DM], g_Wvl[DM * DM];
__device__ __nv_bfloat16 g_Woh[DM * DM], g_Wol[DM * DM];
__device__ __nv_bfloat16 g_Qh [(size_t)BSZ * NH * NSEQ * DH], g_Ql [(size_t)BSZ * NH * NSEQ * DH];
__device__ __nv_bfloat16 g_Kh [(size_t)BSZ * NH * NSEQ * DH], g_Kl [(size_t)BSZ * NH * NSEQ * DH];
__device__ __nv_bfloat16 g_Vth[(size_t)BSZ * NH * DH * NSEQ], g_Vtl[(size_t)BSZ * NH * DH * NSEQ];
__device__ __nv_bfloat16 g_Ph [(size_t)BSZ * NH * NSEQ * NSEQ], g_Pl [(size_t)BSZ * NH * NSEQ * NSEQ];
__device__ __nv_bfloat16 g_Yh [(size_t)BSZ * NSEQ * DM], g_Yl [(size_t)BSZ * NSEQ * DM];

#define CP16(dst, src) \
    asm volatile("cp.async.cg.shared.global [%0], [%1], 16;" :: "r"(dst), "l"(src) : "memory")
#define CP_COMMIT() asm volatile("cp.async.commit_group;" ::: "memory")

// ---------------------------------------------------------------------------
__global__ void w_kernel() {
    int i = blockIdx.x * 256 + threadIdx.x;
    double w = exp(-2.0 * (double)i / (double)DM * log(10000.0));
    float whi = (float)w;
    g_Wf[i] = make_float2(whi, (float)(w - (double)whi));
}

__global__ void ap_kernel() {
    int idx = blockIdx.x * 256 + threadIdx.x;        // 0 .. NSEQ*NSEQ/2-1
    int p = idx >> 10;
    int i = idx & 1023;
    float2 w = g_Wf[i];
    float fp = (float)p;
    float h = fp * w.x;
    float e = fmaf(fp, w.x, -h);
    float t = fmaf(fp, w.y, e);

    constexpr double PI2D = 6.2831853071795864769252867665590058;
    constexpr float CW_A = 6.28125f;
    constexpr float CW_B = (float)(PI2D - (double)CW_A);
    constexpr float CW_C = (float)(PI2D - (double)CW_A - (double)CW_B);
    const float INV2PI = 0.15915494309189535f;

    float fn = rintf(h * INV2PI);
    float r = fmaf(-fn, CW_A, h);
    r = fmaf(-fn, CW_B, r);
    r = fmaf(-fn, CW_C, r);
    r += t;
    float s, c;
    sincosf(r, &s, &c);
    *(float2*)&g_AP[((size_t)p << 11) + 2 * i] = make_float2(s, c);
}

__device__ __forceinline__ void split_pack(float4 v, uint2& hi, uint2& lo) {
    __nv_bfloat162 h0 = __floats2bfloat162_rn(v.x, v.y);
    __nv_bfloat162 h1 = __floats2bfloat162_rn(v.z, v.w);
    float2 f0 = __bfloat1622float2(h0);
    float2 f1 = __bfloat1622float2(h1);
    __nv_bfloat162 l0 = __floats2bfloat162_rn(v.x - f0.x, v.y - f0.y);
    __nv_bfloat162 l1 = __floats2bfloat162_rn(v.z - f1.x, v.w - f1.y);
    hi = make_uint2(*(unsigned*)&h0, *(unsigned*)&h1);
    lo = make_uint2(*(unsigned*)&l0, *(unsigned*)&l1);
}

__global__ __launch_bounds__(256) void conv_kernel(const float* __restrict__ src,
                                                   __nv_bfloat16* __restrict__ dh,
                                                   __nv_bfloat16* __restrict__ dl) {
    size_t i4 = ((size_t)blockIdx.x * 256 + threadIdx.x) * 4;
    float4 v = *(const float4*)&src[i4];
    uint2 hi, lo;
    split_pack(v, hi, lo);
    *(uint2*)&dh[i4] = hi;
    *(uint2*)&dl[i4] = lo;
}

// ---------------------------------------------------------------------------
__device__ __forceinline__ void mma(float* c, const unsigned* a, unsigned b0, unsigned b1) {
    asm volatile(
        "mma.sync.aligned.m16n8k16.row.col.f32.bf16.bf16.f32 "
        "{%0,%1,%2,%3},{%4,%5,%6,%7},{%8,%9},{%0,%1,%2,%3};"
        : "+f"(c[0]), "+f"(c[1]), "+f"(c[2]), "+f"(c[3])
        : "r"(a[0]), "r"(a[1]), "r"(a[2]), "r"(a[3]), "r"(b0), "r"(b1));
}

__device__ __forceinline__ void ldsm_x4(unsigned* r, unsigned addr) {
    asm volatile("ldmatrix.sync.aligned.m8n8.x4.shared.b16 {%0,%1,%2,%3}, [%4];"
                 : "=r"(r[0]), "=r"(r[1]), "=r"(r[2]), "=r"(r[3]) : "r"(addr));
}

// ---------------------------------------------------------------------------
// Tensor-core NT GEMM over pre-split bf16 operands, 128x128x32 tiles, 8 warps,
// two cp.async stages, ldmatrix fragment loads.
// ---------------------------------------------------------------------------
template <int EPI>
__global__ __launch_bounds__(256, 2) void tgemm(float* __restrict__ Cext,
                                                const int* __restrict__ mask) {
    constexpr int K    = (EPI == 3) ? 128 : (EPI == 4 ? 2048 : 1024);
    constexpr bool ATR = (EPI == 4);
    constexpr int NBLK = K / 32;

    extern __shared__ __nv_bfloat16 sm[];
    const unsigned smem_u32 = (unsigned)__cvta_generic_to_shared(sm);

    const int t    = threadIdx.x;
    const int lane = t & 31;
    const int warp = t >> 5;
    const int wm   = warp >> 2;
    const int wn   = warp & 3;
    const int grp  = lane >> 2;
    const int t4   = lane & 3;

    const int bm = blockIdx.y * 128;
    const int bn = blockIdx.x * 128;
    const int bh = (EPI == 3 || EPI == 4) ? blockIdx.z : 0;

    const __nv_bfloat16 *Ah, *Al, *Bh, *Bl;
    if (EPI == 0)      { Ah = g_xh; Al = g_xl; Bh = g_Wqh; Bl = g_Wql; }
    else if (EPI == 1) { Ah = g_xh; Al = g_xl; Bh = g_Wkh; Bl = g_Wkl; }
    else if (EPI == 2) { Ah = g_xh; Al = g_xl; Bh = g_Wvh; Bl = g_Wvl; }
    else if (EPI == 3) {
        size_t off = (size_t)bh * NSEQ * DH;
        Ah = g_Qh + off; Al = g_Ql + off; Bh = g_Kh + off; Bl = g_Kl + off;
    } else if (EPI == 4) {
        size_t ao = (size_t)bh * NSEQ * NSEQ, bo = (size_t)bh * DH * NSEQ;
        Ah = g_Ph + ao; Al = g_Pl + ao; Bh = g_Vth + bo; Bl = g_Vtl + bo;
    } else             { Ah = g_Yh; Al = g_Yl; Bh = g_Woh; Bl = g_Wol; }

    // cp.async staging of one 128x32 bf16 tile set (skips A when ATR)
    auto stage_cp = [&](int k0, int stg) {
        unsigned smb = smem_u32 + (unsigned)(stg * SSTR * 2);
#pragma unroll
        for (int arr = (ATR ? 2 : 0); arr < 4; arr++) {
            const __nv_bfloat16* g = (arr == 0) ? Ah : (arr == 1) ? Al
                                   : (arr == 2) ? Bh : Bl;
            const int rc = (arr < 2) ? bm : bn;
#pragma unroll
            for (int r = 0; r < 2; r++) {
                int chunk = t + 256 * r;
                int row = chunk >> 2;
                int cb  = (chunk & 3) * 8;
                CP16(smb + (unsigned)((arr * TILE + row * LDK + cb) * 2),
                     g + (size_t)(rc + row) * K + k0 + cb);
            }
        }
    };

    // ATR (P^T) staging: loads issued early into regs, stores after MMAs
    uint2 avh[4], avl[4];
    auto atr_load = [&](int k0) {
#pragma unroll
        for (int r = 0; r < 4; r++) {
            int id = t + 256 * r;
            int kk = id >> 5;
            int mc = (id & 31) * 4;
            avh[r] = *(const uint2*)&Ah[(size_t)(k0 + kk) * K + bm + mc];
            avl[r] = *(const uint2*)&Al[(size_t)(k0 + kk) * K + bm + mc];
        }
    };
    auto atr_store = [&](int stg) {
        __nv_bfloat16* As_h = sm + stg * SSTR;
        __nv_bfloat16* As_l = As_h + TILE;
#pragma unroll
        for (int r = 0; r < 4; r++) {
            int id = t + 256 * r;
            int kk = id >> 5;
            int mc = (id & 31) * 4;
            __nv_bfloat162 h0 = *(__nv_bfloat162*)&avh[r].x;
            __nv_bfloat162 h1 = *(__nv_bfloat162*)&avh[r].y;
            __nv_bfloat162 l0 = *(__nv_bfloat162*)&avl[r].x;
            __nv_bfloat162 l1 = *(__nv_bfloat162*)&avl[r].y;
            As_h[(mc + 0) * LDK + kk] = __low2bfloat16(h0);
            As_h[(mc + 1) * LDK + kk] = __high2bfloat16(h0);
            As_h[(mc + 2) * LDK + kk] = __low2bfloat16(h1);
            As_h[(mc + 3) * LDK + kk] = __high2bfloat16(h1);
            As_l[(mc + 0) * LDK + kk] = __low2bfloat16(l0);
            As_l[(mc + 1) * LDK + kk] = __high2bfloat16(l0);
            As_l[(mc + 2) * LDK + kk] = __low2bfloat16(l1);
            As_l[(mc + 3) * LDK + kk] = __high2bfloat16(l1);
        }
    };

    float acc[4][4][4];
#pragma unroll
    for (int i = 0; i < 4; i++)
#pragma unroll
        for (int j = 0; j < 4; j++)
#pragma unroll
            for (int q = 0; q < 4; q++) acc[i][j][q] = 0.f;

    // ldmatrix per-lane address components (row = base + (lane&15),
    // col = ks + (lane>>4)*8) — conflict-free with LDK=40.
    const int lrow = lane & 15;
    const int lcol = (lane >> 4) * 8;

    // prologue
    if (ATR) { atr_load(0); atr_store(0); }
    stage_cp(0, 0);
    CP_COMMIT();

    for (int blk = 0; blk < NBLK; blk++) {
        const int cur = blk & 1;
        if (blk + 1 < NBLK) {
            if (ATR) atr_load((blk + 1) * 32);
            stage_cp((blk + 1) * 32, cur ^ 1);
            CP_COMMIT();
            asm volatile("cp.async.wait_group 1;" ::: "memory");
        } else {
            asm volatile("cp.async.wait_group 0;" ::: "memory");
        }
        __syncthreads();

        const unsigned sA_h = smem_u32 + (unsigned)(cur * SSTR * 2);
        const unsigned sA_l = sA_h + TILE * 2;
        const unsigned sB_h = sA_l + TILE * 2;
        const unsigned sB_l = sB_h + TILE * 2;

#pragma unroll
        for (int ks = 0; ks < 32; ks += 16) {
            // B frags: x4 over 16 n-rows x 2 k-halves -> b0/b1 of two nt tiles
            unsigned bh4[2][4], bl4[2][4];
#pragma unroll
            for (int np = 0; np < 2; np++) {
                unsigned off = (unsigned)(((wn * 32 + np * 16 + lrow) * LDK + ks + lcol) * 2);
                ldsm_x4(bh4[np], sB_h + off);
                ldsm_x4(bl4[np], sB_l + off);
            }
#pragma unroll
            for (int mt = 0; mt < 4; mt++) {
                unsigned off = (unsigned)(((wm * 64 + mt * 16 + lrow) * LDK + ks + lcol) * 2);
                unsigned ah[4], al[4];
                ldsm_x4(ah, sA_h + off);
                ldsm_x4(al, sA_l + off);
#pragma unroll
                for (int nt = 0; nt < 4; nt++) {
                    const int np = nt >> 1, o = nt & 1;
                    mma(acc[mt][nt], ah, bh4[np][o], bh4[np][2 + o]);
                    mma(acc[mt][nt], ah, bl4[np][o], bl4[np][2 + o]);
                    mma(acc[mt][nt], al, bh4[np][o], bh4[np][2 + o]);
                }
            }
        }

        if (ATR && blk + 1 < NBLK) atr_store(cur ^ 1);
        __syncthreads();
    }

    // ---- epilogue ----
#pragma unroll
    for (int mt = 0; mt < 4; mt++) {
#pragma unroll
        for (int nt = 0; nt < 4; nt++) {
#pragma unroll
            for (int half = 0; half < 2; half++) {
                const int row = bm + wm * 64 + mt * 16 + grp + half * 8;
                const int col = bn + wn * 32 + nt * 8 + t4 * 2;
                const float vx = acc[mt][nt][half * 2 + 0];
                const float vy = acc[mt][nt][half * 2 + 1];
                if (EPI <= 1) {
                    __nv_bfloat162 h = __floats2bfloat162_rn(vx, vy);
                    float2 f = __bfloat1622float2(h);
                    __nv_bfloat162 l = __floats2bfloat162_rn(vx - f.x, vy - f.y);
                    int b = row >> 11, n = row & (NSEQ - 1);
                    int hh = col >> 7, e = col & (DH - 1);
                    size_t o = (((size_t)b * NH + hh) * NSEQ + n) * DH + e;
                    if (EPI == 0) { *(__nv_bfloat162*)&g_Qh[o] = h; *(__nv_bfloat162*)&g_Ql[o] = l; }
                    else          { *(__nv_bfloat162*)&g_Kh[o] = h; *(__nv_bfloat162*)&g_Kl[o] = l; }
                } else if (EPI == 2) {
                    int b = row >> 11, n = row & (NSEQ - 1);
                    int hh = col >> 7, e = col & (DH - 1);
                    size_t o = (((size_t)b * NH + hh) * DH + e) * NSEQ + n;
                    __nv_bfloat16 hx = __float2bfloat16_rn(vx);
                    __nv_bfloat16 lx = __float2bfloat16_rn(vx - __bfloat162float(hx));
                    __nv_bfloat16 hy = __float2bfloat16_rn(vy);
                    __nv_bfloat16 ly = __float2bfloat16_rn(vy - __bfloat162float(hy));
                    g_Vth[o] = hx;           g_Vtl[o] = lx;
                    g_Vth[o + NSEQ] = hy;    g_Vtl[o + NSEQ] = ly;
                } else if (EPI == 3) {
                    int b = bh >> 3;
                    bool mrow = (mask[b * NSEQ + row] != 0);
                    size_t so = (size_t)bh * NSEQ * NSEQ + (size_t)row * NSEQ + col;
                    size_t apo = (size_t)row * NSEQ + col;
                    bool ok0 = mrow && (mask[b * NSEQ + col] != 0);
                    bool ok1 = mrow && (mask[b * NSEQ + col + 1] != 0);
                    g_S[so]     = ok0 ? (vx + g_AP[apo])     : NEG_INF_F;
                    g_S[so + 1] = ok1 ? (vy + g_AP[apo + 1]) : NEG_INF_F;
                } else if (EPI == 4) {
                    int b = bh >> 3, hh = bh & 7;
                    size_t o = ((size_t)b * NSEQ + row) * DM + hh * DH + col;
                    __nv_bfloat162 h = __floats2bfloat162_rn(vx, vy);
                    float2 f = __bfloat1622float2(h);
                    __nv_bfloat162 l = __floats2bfloat162_rn(vx - f.x, vy - f.y);
                    *(__nv_bfloat162*)&g_Yh[o] = h;
                    *(__nv_bfloat162*)&g_Yl[o] = l;
                } else {
                    Cext[(size_t)row * DM + col]     = vx;
                    Cext[(size_t)row * DM + col + 1] = vy;
                }
            }
        }
    }
}

// ---------------------------------------------------------------------------
// Fused softmax: reads S fp32, writes P as bf16 hi/lo pairs; head-7 rows also
// stream fp32 to d_out's A region.
// ---------------------------------------------------------------------------
__global__ __launch_bounds__(256) void softmax_kernel(float* __restrict__ Aout) {
    __shared__ float red[8];
    __shared__ float bcast;
    const int row = blockIdx.x;
    const float* S = g_S + (size_t)row * NSEQ;
    const int t = threadIdx.x, lane = t & 31, warp = t >> 5;

    float4 v0 = *(const float4*)&S[t * 4];
    float4 v1 = *(const float4*)&S[(t + 256) * 4];

    float m = fmaxf(fmaxf(fmaxf(v0.x, v0.y), fmaxf(v0.z, v0.w)),
                    fmaxf(fmaxf(v1.x, v1.y), fmaxf(v1.z, v1.w)));
#pragma unroll
    for (int o = 16; o; o >>= 1) m = fmaxf(m, __shfl_xor_sync(~0u, m, o));
    if (lane == 0) red[warp] = m;
    __syncthreads();
    if (t == 0) {
        float mm = red[0];
#pragma unroll
        for (int i = 1; i < 8; i++) mm = fmaxf(mm, red[i]);
        bcast = mm;
    }
    __syncthreads();
    m = bcast;

    float4 p0, p1;
    p0.x = expf(v0.x - m); p0.y = expf(v0.y - m);
    p0.z = expf(v0.z - m); p0.w = expf(v0.w - m);
    p1.x = expf(v1.x - m); p1.y = expf(v1.y - m);
    p1.z = expf(v1.z - m); p1.w = expf(v1.w - m);

    float z = p0.x + p0.y + p0.z + p0.w + p1.x + p1.y + p1.z + p1.w;
#pragma unroll
    for (int o = 16; o; o >>= 1) z += __shfl_xor_sync(~0u, z, o);
    if (lane == 0) red[warp] = z;
    __syncthreads();
    if (t == 0) {
        float zz = 0.f;
#pragma unroll
        for (int i = 0; i < 8; i++) zz += red[i];
        bcast = 1.f / zz;
    }
    __syncthreads();
    float zi = bcast;

    p0.x *= zi; p0.y *= zi; p0.z *= zi; p0.w *= zi;
    p1.x *= zi; p1.y *= zi; p1.z *= zi; p1.w *= zi;

    size_t pb = (size_t)row * NSEQ;
    uint2 hi, lo;
    split_pack(p0, hi, lo);
    *(uint2*)&g_Ph[pb + t * 4] = hi;
    *(uint2*)&g_Pl[pb + t * 4] = lo;
    split_pack(p1, hi, lo);
    *(uint2*)&g_Ph[pb + (t + 256) * 4] = hi;
    *(uint2*)&g_Pl[pb + (t + 256) * 4] = lo;

    const int bhh = row >> 11;
    if ((bhh & 7) == 7) {
        const int b = bhh >> 3;
        size_t base = OUT_A_OFF + ((size_t)b * NSEQ + (row & (NSEQ - 1))) * NSEQ;
        *(float4*)&Aout[base + t * 4]         = p0;
        *(float4*)&Aout[base + (t + 256) * 4] = p1;
    }
}

// ---------------------------------------------------------------------------
extern "C" void kernel_launch(void* const* d_in, const int* in_sizes, int n_in,
                              void* d_out, int out_size) {
    const float* x    = (const float*)d_in[0];
    const int*   mask = (const int*)  d_in[1];
    const float* Wq   = (const float*)d_in[2];
    const float* Wk   = (const float*)d_in[3];
    const float* Wv   = (const float*)d_in[4];
    const float* Wout = (const float*)d_in[5];
    float* out = (float*)d_out;

    cudaFuncSetAttribute(tgemm<0>, cudaFuncAttributeMaxDynamicSharedMemorySize, SMEM_BYTES);
    cudaFuncSetAttribute(tgemm<1>, cudaFuncAttributeMaxDynamicSharedMemorySize, SMEM_BYTES);
    cudaFuncSetAttribute(tgemm<2>, cudaFuncAttributeMaxDynamicSharedMemorySize, SMEM_BYTES);
    cudaFuncSetAttribute(tgemm<3>, cudaFuncAttributeMaxDynamicSharedMemorySize, SMEM_BYTES);
    cudaFuncSetAttribute(tgemm<4>, cudaFuncAttributeMaxDynamicSharedMemorySize, SMEM_BYTES);
    cudaFuncSetAttribute(tgemm<5>, cudaFuncAttributeMaxDynamicSharedMemorySize, SMEM_BYTES);

    // operand pre-split (tiny, bandwidth-bound)
    __nv_bfloat16 *xh, *xl, *wqh, *wql, *wkh, *wkl, *wvh, *wvl, *woh, *wol;
    cudaGetSymbolAddress((void**)&xh,  g_xh);  cudaGetSymbolAddress((void**)&xl,  g_xl);
    cudaGetSymbolAddress((void**)&wqh, g_Wqh); cudaGetSymbolAddress((void**)&wql, g_Wql);
    cudaGetSymbolAddress((void**)&wkh, g_Wkh); cudaGetSymbolAddress((void**)&wkl, g_Wkl);
    cudaGetSymbolAddress((void**)&wvh, g_Wvh); cudaGetSymbolAddress((void**)&wvl, g_Wvl);
    cudaGetSymbolAddress((void**)&woh, g_Woh); cudaGetSymbolAddress((void**)&wol, g_Wol);

    conv_kernel<<<(BSZ * NSEQ * DM) / 1024, 256>>>(x, xh, xl);
    conv_kernel<<<(DM * DM) / 1024, 256>>>(Wq, wqh, wql);
    conv_kernel<<<(DM * DM) / 1024, 256>>>(Wk, wkh, wkl);
    conv_kernel<<<(DM * DM) / 1024, 256>>>(Wv, wvh, wvl);
    conv_kernel<<<(DM * DM) / 1024, 256>>>(Wout, woh, wol);

    w_kernel<<<4, 256>>>();
    ap_kernel<<<((size_t)NSEQ * NSEQ / 2) / 256, 256>>>();

    dim3 gproj(DM / 128, (BSZ * NSEQ) / 128);          // (8, 64)
    tgemm<0><<<gproj, 256, SMEM_BYTES>>>(nullptr, nullptr);
    tgemm<1><<<gproj, 256, SMEM_BYTES>>>(nullptr, nullptr);
    tgemm<2><<<gproj, 256, SMEM_BYTES>>>(nullptr, nullptr);

    tgemm<3><<<dim3(NSEQ / 128, NSEQ / 128, BSZ * NH), 256, SMEM_BYTES>>>(nullptr, mask);

    softmax_kernel<<<BSZ * NH * NSEQ, 256>>>(out);

    tgemm<4><<<dim3(1, NSEQ / 128, BSZ * NH), 256, SMEM_BYTES>>>(nullptr, nullptr);

    tgemm<5><<<gproj, 256, SMEM_BYTES>>>(out, nullptr);
}